// round 14
// baseline (speedup 1.0000x reference)
#include <cuda_runtime.h>
#include <cuda_fp16.h>
#include <mma.h>
#include <cstdint>
#include <math.h>

using namespace nvcuda;

#define Hdim 1024
#define INdim 512
#define Bdim 256
#define Tdim 256
#define HB (Hdim * Bdim)          // 262144 elements
#define XT_STRIDE (INdim * Bdim)
#define NBLOCKS 128
#define KC 64                     // k per stream chunk
#define NCHUNK 16                 // 1024 / 64

// recurrence smem: resident K-slice 64x1024 + 4-stage W/r/m stream buffers
#define A_LD 1032                 // 1024 + 8 pad halfs
#define SA_HALFS (64 * A_LD)      // 66048 halfs = 132096 B
#define W_LD 72
#define W_STAGE (64 * W_LD)       // 4608 halfs = 9216 B
#define R_LD 40
#define R_STAGE (64 * R_LD)       // 2560 halfs = 5120 B
#define SMEM_REC ((SA_HALFS + 4 * W_STAGE + 8 * R_STAGE) * 2)  // 209920 B
#define G_LD 36                   // floats; G tiles alias the W stages

// proj smem: A,B double-buffered tiles (A 128x32, B 32x128)
#define KCHUNK 32
#define A_LDP 40
#define B_LDP 136
#define SA_P (128 * A_LDP)
#define SB_P (KCHUNK * B_LDP)
#define SMEM_PROJ (2 * (SA_P + SB_P) * 2)  // 37888 bytes

// ---------------- device scratch (no cudaMalloc allowed) ----------------
// ONLY referenced in device code (host-arg binding of __device__ globals
// silently resolves to the host shadow on GB300 ATS — the R4/R5 bug).
__device__ __align__(1024) float g_Az[(size_t)Tdim * HB];   // 256 MiB
__device__ __align__(1024) float g_Ar[(size_t)Tdim * HB];   // 256 MiB
__device__ __align__(1024) __half g_xh[(size_t)Tdim * XT_STRIDE];  // 64 MiB
__device__ __align__(1024) __half g_Kh[Hdim * Hdim];
__device__ __align__(1024) __half g_Wh[Hdim * Hdim];
__device__ __align__(1024) __half g_Pzh[Hdim * INdim];
__device__ __align__(1024) __half g_Prh[Hdim * INdim];
__device__ __align__(1024) __half g_rh[2 * HB];  // parity double-buffered
__device__ __align__(1024) __half g_mh[2 * HB];
__device__ unsigned long long g_barrier;  // monotonic, never reset

// ---------------- helpers ----------------
__device__ __forceinline__ float sigm(float x) {
    return 1.0f / (1.0f + __expf(-x));
}
__device__ __forceinline__ uint32_t s2u(const void* p) {
    return (uint32_t)__cvta_generic_to_shared(p);
}
__device__ __forceinline__ void cp_async16_ca(uint32_t saddr, const void* g) {
    asm volatile("cp.async.ca.shared.global [%0], [%1], 16;"
                 :: "r"(saddr), "l"(g));
}
__device__ __forceinline__ void cp_async16_cg(uint32_t saddr, const void* g) {
    asm volatile("cp.async.cg.shared.global [%0], [%1], 16;"
                 :: "r"(saddr), "l"(g));
}
__device__ __forceinline__ void cp_commit() {
    asm volatile("cp.async.commit_group;" ::: "memory");
}
template <int N>
__device__ __forceinline__ void cp_wait() {
    asm volatile("cp.async.wait_group %0;" :: "n"(N) : "memory");
}

// Flat grid barrier (proven in R11): monotonic counter, release-RMW arrive,
// acquire-load poll.
__device__ __forceinline__ void grid_sync() {
    __syncthreads();
    if (threadIdx.x == 0) {
        unsigned long long old;
        asm volatile("atom.release.gpu.global.add.u64 %0, [%1], 1;"
                     : "=l"(old) : "l"(&g_barrier) : "memory");
        const unsigned long long target = (old / NBLOCKS + 1) * NBLOCKS;
        unsigned long long cur;
        do {
            asm volatile("ld.acquire.gpu.global.u64 %0, [%1];"
                         : "=l"(cur) : "l"(&g_barrier) : "memory");
        } while (cur < target);
    }
    __syncthreads();
}

// ---------------- weight conversion: fp32 -> fp16 (one launch) -----------
__global__ __launch_bounds__(256) void conv_weights(
    const float* __restrict__ Km, const float* __restrict__ Wr,
    const float* __restrict__ Pz, const float* __restrict__ Pr)
{
    const size_t i = ((size_t)blockIdx.x * 256 + threadIdx.x) * 4;
    const float* src;
    __half* dst;
    size_t off;
    if (i < (size_t)Hdim * Hdim) { src = Km; dst = g_Kh; off = i; }
    else if (i < 2ull * Hdim * Hdim) {
        src = Wr; dst = g_Wh; off = i - (size_t)Hdim * Hdim;
    } else if (i < 2ull * Hdim * Hdim + (size_t)Hdim * INdim) {
        src = Pz; dst = g_Pzh; off = i - 2ull * Hdim * Hdim;
    } else {
        src = Pr; dst = g_Prh; off = i - 2ull * Hdim * Hdim - (size_t)Hdim * INdim;
    }
    float4 v = *(const float4*)&src[off];
    __half h[4] = { __float2half_rn(v.x), __float2half_rn(v.y),
                    __float2half_rn(v.z), __float2half_rn(v.w) };
    *(uint2*)&dst[off] = *(uint2*)h;
}

__global__ __launch_bounds__(256) void conv_x(const float* __restrict__ x) {
    const size_t i = ((size_t)blockIdx.x * 256 + threadIdx.x) * 4;
    float4 v = *(const float4*)&x[i];
    __half h[4] = { __float2half_rn(v.x), __float2half_rn(v.y),
                    __float2half_rn(v.z), __float2half_rn(v.w) };
    *(uint2*)&g_xh[i] = *(uint2*)h;
}

// ---------------- projection GEMM: Az/Ar[t] = P @ x_t --------------------
// Block tile 128x128, warp tile 32x64 (4x2 warps). grid (8, 2, 2*Tdim).
__global__ __launch_bounds__(256, 2) void proj_gemm() {
    extern __shared__ __half smh[];
    const int tid = threadIdx.x;
    const int warp = tid >> 5;
    const int wm = warp >> 1, wn = warp & 1;
    const int which = blockIdx.z & 1, q = blockIdx.z >> 1;
    const __half* A = which ? g_Prh : g_Pzh;
    const __half* B = g_xh + (size_t)q * XT_STRIDE;
    float* C = (which ? g_Ar : g_Az) + (size_t)q * HB;
    const int m0 = blockIdx.x * 128, n0 = blockIdx.y * 128;

    __half* const sA[2] = { smh, smh + SA_P };
    __half* const sB[2] = { smh + 2 * SA_P, smh + 2 * SA_P + SB_P };
    const uint32_t aB[2] = { s2u(sA[0]), s2u(sA[1]) };
    const uint32_t bB[2] = { s2u(sB[0]), s2u(sB[1]) };

    auto issue = [&](int c, int s) {
        const int kc = c * KCHUNK;
#pragma unroll
        for (int i = 0; i < 2; ++i) {
            const int e = i * 256 + tid, r = e >> 2, f8 = e & 3;
            cp_async16_ca(aB[s] + (uint32_t)(r * A_LDP + f8 * 8) * 2,
                          A + (size_t)(m0 + r) * INdim + kc + f8 * 8);
        }
#pragma unroll
        for (int i = 0; i < 2; ++i) {
            const int e = i * 256 + tid, r = e >> 4, f8 = e & 15;
            cp_async16_ca(bB[s] + (uint32_t)(r * B_LDP + f8 * 8) * 2,
                          B + (size_t)(kc + r) * Bdim + n0 + f8 * 8);
        }
        cp_commit();
    };

    wmma::fragment<wmma::accumulator, 16, 16, 16, float> acc[2][4];
#pragma unroll
    for (int i = 0; i < 2; ++i)
#pragma unroll
        for (int j = 0; j < 4; ++j) wmma::fill_fragment(acc[i][j], 0.0f);

    const int nChunks = INdim / KCHUNK;  // 16
    issue(0, 0);
    for (int c = 0; c < nChunks; ++c) {
        if (c + 1 < nChunks) { issue(c + 1, (c + 1) & 1); cp_wait<1>(); }
        else                 { cp_wait<0>(); }
        __syncthreads();
        const __half* cA = sA[c & 1];
        const __half* cB = sB[c & 1];
#pragma unroll
        for (int ks = 0; ks < 2; ++ks) {
            wmma::fragment<wmma::matrix_a, 16, 16, 16, __half,
                           wmma::row_major> af[2];
            wmma::fragment<wmma::matrix_b, 16, 16, 16, __half,
                           wmma::row_major> bf[4];
#pragma unroll
            for (int i = 0; i < 2; ++i)
                wmma::load_matrix_sync(af[i],
                    cA + (wm * 32 + i * 16) * A_LDP + ks * 16, A_LDP);
#pragma unroll
            for (int j = 0; j < 4; ++j)
                wmma::load_matrix_sync(bf[j],
                    cB + (ks * 16) * B_LDP + wn * 64 + j * 16, B_LDP);
#pragma unroll
            for (int i = 0; i < 2; ++i)
#pragma unroll
                for (int j = 0; j < 4; ++j)
                    wmma::mma_sync(acc[i][j], af[i], bf[j], acc[i][j]);
        }
        __syncthreads();
    }
    const int row = m0 + wm * 32, col = n0 + wn * 64;
#pragma unroll
    for (int i = 0; i < 2; ++i)
#pragma unroll
        for (int j = 0; j < 4; ++j)
            wmma::store_matrix_sync(
                C + (size_t)(row + i * 16) * Bdim + col + j * 16,
                acc[i][j], Bdim, wmma::mem_row_major);
}

// ---------------- persistent recurrence: ONE grid-sync per step ----------
// 128 blocks (mb16 x nb8) x 256 threads, 1 block/SM (210KB smem).
// Each block computes BOTH G1 = K@r and G2 = w_r@m for its own 64h x 32b
// output tile over FULL K, then does the elem update locally (partials
// reduced in smem) — no global partial round-trip, one barrier per step.
// Warps: g = gemm (G1/G2), kp = k-parity (even/odd chunks), wm; warp tile
// 32x32 (1:1 LDS:mma). K-slice resident in smem; W/r/m streamed (4-stage).
// r/m parity double-buffered (others may still stream r_t while we write
// r_{t+1}).
__global__ __launch_bounds__(256, 1) void recurrence(
    const float* __restrict__ c_x, const float* __restrict__ c_u,
    const float* __restrict__ c_U, const float* __restrict__ gz,
    const float* __restrict__ br)
{
    extern __shared__ __half smh[];
    const int tid = threadIdx.x;
    const int bid = blockIdx.x;
    const int mb = bid >> 3, nb = bid & 7;
    const int m0 = mb * 64, n0 = nb * 32;

    // ----- elem identity: 1 row x 8 consecutive b cols of the tile -----
    const int row = tid >> 2;           // 0..63
    const int b8 = (tid & 3) * 8;       // 0,8,16,24
    const int h = m0 + row;
    const int idx = h * 256 + n0 + b8;
    const float zx = 0.001f + 0.099f * sigm(c_x[h]);
    const float zu = 0.001f + 0.099f * sigm(c_u[h]);
    const float Uc = 0.9f * sigm(c_U[h]);
    const float gzh = gz[h], brh = br[h];
    float v[8], X[8], U[8];
#pragma unroll
    for (int e = 0; e < 8; ++e) { v[e] = 0.f; X[e] = 1.f; U[e] = 0.9f; }

    // ----- gemm identity -----
    const int warp = tid >> 5;
    const int g = warp >> 2;            // 0 = G1 (K@r), 1 = G2 (W@m)
    const int kp = (warp >> 1) & 1;     // chunk parity
    const int wm = warp & 1;            // m-half of 64

    __half* const sA = smh;                              // resident K slice
    __half* const sW = smh + SA_HALFS;                   // 4 W stages
    __half* const sR = sW + 4 * W_STAGE;                 // 4 r stages
    __half* const sM = sR + 4 * R_STAGE;                 // 4 m stages
    float* const sG = (float*)sW;                        // aliases W stages
    const uint32_t aBase = s2u(sA), wBase = s2u(sW);
    const uint32_t rBase = s2u(sR), mBase = s2u(sM);

    // ----- one-time resident K-slice load: 64 x 1024 halfs ----
    {
        const __half* Asrc = g_Kh + (size_t)m0 * Hdim;
#pragma unroll
        for (int i = 0; i < 32; ++i) {
            const int e = i * 256 + tid, r_ = e >> 7, g8 = e & 127;
            cp_async16_ca(aBase + (uint32_t)(r_ * A_LD + g8 * 8) * 2,
                          Asrc + (size_t)r_ * Hdim + g8 * 8);
        }
        cp_commit();
        cp_wait<0>();
        __syncthreads();
    }

    const __half* rsrc;
    const __half* msrc;
    auto issue = [&](int c) {
        const int s = c & 3;
#pragma unroll
        for (int i = 0; i < 2; ++i) {  // W chunk: 64 x 64 halfs
            const int e = i * 256 + tid, r_ = e >> 3, g8 = e & 7;
            cp_async16_ca(wBase + (uint32_t)(s * W_STAGE + r_ * W_LD + g8 * 8) * 2,
                          g_Wh + (size_t)(m0 + r_) * Hdim + c * KC + g8 * 8);
        }
        {  // r, m chunks: 64 x 32 halfs each (bypass L1 — rewritten per step)
            const int r_ = tid >> 2, g4 = tid & 3;
            cp_async16_cg(rBase + (uint32_t)(s * R_STAGE + r_ * R_LD + g4 * 8) * 2,
                          rsrc + (size_t)(c * KC + r_) * Bdim + n0 + g4 * 8);
            cp_async16_cg(mBase + (uint32_t)(s * R_STAGE + r_ * R_LD + g4 * 8) * 2,
                          msrc + (size_t)(c * KC + r_) * Bdim + n0 + g4 * 8);
        }
        cp_commit();
    };

    // ----- initial elem (t = 0): v=0 -> r_0, m_0 into parity 0 -----
    {
        __half rr[8], mm[8];
#pragma unroll
        for (int e = 0; e < 8; ++e) {
            const float r = sigm(v[e]);
            float Xn = zx + (1.0f - zx) * X[e] - U[e] * X[e] * r;
            float Un = Uc * zu + (1.0f - zu) * U[e] + Uc * (1.0f - U[e]) * r;
            Un = fminf(fmaxf(Un, Uc), 1.0f);
            X[e] = Xn;
            U[e] = Un;
            rr[e] = __float2half_rn(r);
            mm[e] = __float2half_rn(Un * Xn * r);
        }
        *(uint4*)&g_rh[idx] = *(uint4*)rr;
        *(uint4*)&g_mh[idx] = *(uint4*)mm;
    }
    grid_sync();

    for (int t = 0; t < Tdim; ++t) {
        const int par = t & 1;
        rsrc = g_rh + (size_t)par * HB;
        msrc = g_mh + (size_t)par * HB;

        // prefetch this step's Az/Ar (independent of everything here)
        const size_t off = (size_t)t * HB + idx;
        float az[8], ar[8];
        *(float4*)&az[0] = *(const float4*)&g_Az[off];
        *(float4*)&az[4] = *(const float4*)&g_Az[off + 4];
        *(float4*)&ar[0] = *(const float4*)&g_Ar[off];
        *(float4*)&ar[4] = *(const float4*)&g_Ar[off + 4];

        wmma::fragment<wmma::accumulator, 16, 16, 16, float> acc[2][2];
#pragma unroll
        for (int i = 0; i < 2; ++i)
#pragma unroll
            for (int j = 0; j < 2; ++j) wmma::fill_fragment(acc[i][j], 0.0f);

        issue(0); issue(1); issue(2);
        for (int c = 0; c < NCHUNK; ++c) {
            if (c <= 13)      cp_wait<2>();
            else if (c == 14) cp_wait<1>();
            else              cp_wait<0>();
            __syncthreads();           // chunk c visible; prev compute done
            if (c + 3 < NCHUNK) issue(c + 3);
            if ((c & 1) == kp) {
                const int s = c & 3;
#pragma unroll
                for (int ks = 0; ks < 4; ++ks) {
                    wmma::fragment<wmma::matrix_a, 16, 16, 16, __half,
                                   wmma::row_major> af[2];
                    wmma::fragment<wmma::matrix_b, 16, 16, 16, __half,
                                   wmma::row_major> bf[2];
                    if (g == 0) {
#pragma unroll
                        for (int i = 0; i < 2; ++i)
                            wmma::load_matrix_sync(af[i],
                                sA + (wm * 32 + i * 16) * A_LD + c * KC + ks * 16,
                                A_LD);
#pragma unroll
                        for (int j = 0; j < 2; ++j)
                            wmma::load_matrix_sync(bf[j],
                                sR + s * R_STAGE + (ks * 16) * R_LD + j * 16,
                                R_LD);
                    } else {
#pragma unroll
                        for (int i = 0; i < 2; ++i)
                            wmma::load_matrix_sync(af[i],
                                sW + s * W_STAGE + (wm * 32 + i * 16) * W_LD + ks * 16,
                                W_LD);
#pragma unroll
                        for (int j = 0; j < 2; ++j)
                            wmma::load_matrix_sync(bf[j],
                                sM + s * R_STAGE + (ks * 16) * R_LD + j * 16,
                                R_LD);
                    }
#pragma unroll
                    for (int i = 0; i < 2; ++i)
#pragma unroll
                        for (int j = 0; j < 2; ++j)
                            wmma::mma_sync(acc[i][j], af[i], bf[j], acc[i][j]);
                }
            }
        }

        // ----- stage partials to smem (aliases W stages; all reads done) --
        __syncthreads();
        float* Gt = sG + (size_t)(g * 2 + kp) * (64 * G_LD);
#pragma unroll
        for (int i = 0; i < 2; ++i)
#pragma unroll
            for (int j = 0; j < 2; ++j)
                wmma::store_matrix_sync(
                    Gt + (wm * 32 + i * 16) * G_LD + j * 16,
                    acc[i][j], G_LD, wmma::mem_row_major);
        __syncthreads();

        // ----- elem: reduce partials, update v/X/U, emit r/m parity 1-par --
        {
            const float* G1a = sG;
            const float* G1b = sG + 64 * G_LD;
            const float* G2a = sG + 2 * 64 * G_LD;
            const float* G2b = sG + 3 * 64 * G_LD;
            const int go = row * G_LD + b8;
#pragma unroll
            for (int e = 0; e < 8; ++e) {
                const float s1 = G1a[go + e] + G1b[go + e];
                const float s2 = G2a[go + e] + G2b[go + e];
                const float zt = 0.1f * sigm(s1 + az[e] + gzh);
                v[e] = (1.0f - zt) * v[e] + 0.1f * (s2 + ar[e] + brh);
            }
            __stcs((float4*)&g_Az[off], *(float4*)&v[0]);
            __stcs((float4*)&g_Az[off + 4], *(float4*)&v[4]);

            if (t + 1 < Tdim) {
                __half rr[8], mm[8];
#pragma unroll
                for (int e = 0; e < 8; ++e) {
                    const float r = sigm(v[e]);
                    float Xn = zx + (1.0f - zx) * X[e] - U[e] * X[e] * r;
                    float Un = Uc * zu + (1.0f - zu) * U[e] +
                               Uc * (1.0f - U[e]) * r;
                    Un = fminf(fmaxf(Un, Uc), 1.0f);
                    X[e] = Xn;
                    U[e] = Un;
                    rr[e] = __float2half_rn(r);
                    mm[e] = __float2half_rn(Un * Xn * r);
                }
                const size_t widx = (size_t)(1 - par) * HB + idx;
                *(uint4*)&g_rh[widx] = *(uint4*)rr;
                *(uint4*)&g_mh[widx] = *(uint4*)mm;
                grid_sync();
            }
        }
    }
}

// ---------------- final transpose: g_Az[t][h][b] -> out[t][b][h] ---------
__global__ __launch_bounds__(256) void transpose_out(float* __restrict__ out) {
    __shared__ float tile[32][33];
    const int t = blockIdx.z;
    const int h0 = blockIdx.y * 32;
    const int b0 = blockIdx.x * 32;
    const float* src = g_Az + (size_t)t * HB;
    float* dst = out + (size_t)t * HB;
    const int lx = threadIdx.x, ly = threadIdx.y;
#pragma unroll
    for (int i = 0; i < 32; i += 8)
        tile[ly + i][lx] = src[(size_t)(h0 + ly + i) * Bdim + b0 + lx];
    __syncthreads();
#pragma unroll
    for (int i = 0; i < 32; i += 8)
        dst[(size_t)(b0 + ly + i) * Hdim + h0 + lx] = tile[lx][ly + i];
}

// ---------------- launch ----------------
extern "C" void kernel_launch(void* const* d_in, const int* in_sizes, int n_in,
                              void* d_out, int out_size)
{
    const float* x   = (const float*)d_in[0];  // (T, IN, B)
    const float* c_x = (const float*)d_in[1];
    const float* c_u = (const float*)d_in[2];
    const float* c_U = (const float*)d_in[3];
    const float* w_r = (const float*)d_in[4];  // (H,H)
    const float* p_r = (const float*)d_in[5];  // (H,IN)
    const float* b_r = (const float*)d_in[6];
    const float* g_z = (const float*)d_in[7];
    const float* Km  = (const float*)d_in[8];  // (H,H)
    const float* p_z = (const float*)d_in[9];  // (H,IN)
    float* out = (float*)d_out;                // (T, B, H)

    cudaFuncSetAttribute(proj_gemm,
                         cudaFuncAttributeMaxDynamicSharedMemorySize, SMEM_PROJ);
    cudaFuncSetAttribute(recurrence,
                         cudaFuncAttributeMaxDynamicSharedMemorySize, SMEM_REC);

    conv_weights<<<(2 * Hdim * Hdim + 2 * Hdim * INdim) / 1024, 256>>>(
        Km, w_r, p_z, p_r);
    conv_x<<<(int)(((size_t)Tdim * XT_STRIDE) / 1024), 256>>>(x);
    proj_gemm<<<dim3(8, 2, 2 * Tdim), 256, SMEM_PROJ>>>();
    recurrence<<<NBLOCKS, 256, SMEM_REC>>>(c_x, c_u, c_U, g_z, b_r);
    transpose_out<<<dim3(Bdim / 32, Hdim / 32, Tdim), dim3(32, 8)>>>(out);
}

// round 15
// speedup vs baseline: 1.3723x; 1.3723x over previous
#include <cuda_runtime.h>
#include <cuda_fp16.h>
#include <mma.h>
#include <cstdint>
#include <math.h>

using namespace nvcuda;

#define Hdim 1024
#define INdim 512
#define Bdim 256
#define Tdim 256
#define HB (Hdim * Bdim)          // 262144 elements
#define KSPLIT 2
#define XT_STRIDE (INdim * Bdim)
#define NBLOCKS 128
#define KCHUNK 32

// recurrence smem: persistent A slice 128x512 + FULL B slice 512x64 halfs
#define A_LDR 520                 // 512 + 8 pad halfs
#define SA_R (128 * A_LDR)        // 66560 halfs = 133120 B
#define B_LDR 72                  // 64 + 8 pad halfs
#define SB_R (512 * B_LDR)        // 36864 halfs = 73728 B
#define SMEM_REC ((SA_R + SB_R) * 2)  // 206848 bytes

// proj smem: A,B double-buffered tiles (A 128x32, B 32x128)
#define A_LDP 40
#define B_LDP 136
#define SA_P (128 * A_LDP)
#define SB_P (KCHUNK * B_LDP)
#define SMEM_PROJ (2 * (SA_P + SB_P) * 2)  // 37888 bytes

// ---------------- device scratch (no cudaMalloc allowed) ----------------
// ONLY referenced in device code (host-arg binding of __device__ globals
// silently resolves to the host shadow on GB300 ATS — the R4/R5 bug).
__device__ __align__(1024) float g_Az[(size_t)Tdim * HB];   // 256 MiB
__device__ __align__(1024) float g_Ar[(size_t)Tdim * HB];   // 256 MiB
__device__ __align__(1024) __half g_xh[(size_t)Tdim * XT_STRIDE];  // 64 MiB
__device__ __align__(1024) __half g_Kh[Hdim * Hdim];
__device__ __align__(1024) __half g_Wh[Hdim * Hdim];
__device__ __align__(1024) __half g_Pzh[Hdim * INdim];
__device__ __align__(1024) __half g_Prh[Hdim * INdim];
__device__ __align__(1024) __half g_rh[HB];
__device__ __align__(1024) __half g_mh[HB];
__device__ __align__(1024) float g_G1p[KSPLIT * HB];
__device__ __align__(1024) float g_G2p[KSPLIT * HB];
__device__ unsigned long long g_barrier;  // monotonic, never reset

// ---------------- helpers ----------------
__device__ __forceinline__ float sigm(float x) {
    return 1.0f / (1.0f + __expf(-x));
}
__device__ __forceinline__ uint32_t s2u(const void* p) {
    return (uint32_t)__cvta_generic_to_shared(p);
}
__device__ __forceinline__ void cp_async16_ca(uint32_t saddr, const void* g) {
    asm volatile("cp.async.ca.shared.global [%0], [%1], 16;"
                 :: "r"(saddr), "l"(g));
}
__device__ __forceinline__ void cp_async16_cg(uint32_t saddr, const void* g) {
    asm volatile("cp.async.cg.shared.global [%0], [%1], 16;"
                 :: "r"(saddr), "l"(g));
}
__device__ __forceinline__ void cp_commit() {
    asm volatile("cp.async.commit_group;" ::: "memory");
}
template <int N>
__device__ __forceinline__ void cp_wait() {
    asm volatile("cp.async.wait_group %0;" :: "n"(N) : "memory");
}

// Split grid barrier (flat, proven R11 mechanism). arrive: release-RMW on
// monotonic counter (orders all prior stores); wait: acquire-poll. Work
// placed between arrive and wait overlaps other blocks' arrivals — it must
// only touch per-thread-private data.
__device__ __forceinline__ unsigned long long grid_arrive() {
    __syncthreads();
    unsigned long long target = 0;
    if (threadIdx.x == 0) {
        unsigned long long old;
        asm volatile("atom.release.gpu.global.add.u64 %0, [%1], 1;"
                     : "=l"(old) : "l"(&g_barrier) : "memory");
        target = (old / NBLOCKS + 1) * NBLOCKS;
    }
    return target;
}
__device__ __forceinline__ void grid_wait(unsigned long long target) {
    if (threadIdx.x == 0) {
        unsigned long long cur;
        do {
            asm volatile("ld.acquire.gpu.global.u64 %0, [%1];"
                         : "=l"(cur) : "l"(&g_barrier) : "memory");
        } while (cur < target);
    }
    __syncthreads();
}
__device__ __forceinline__ void grid_sync() {
    grid_wait(grid_arrive());
}

// ---------------- weight conversion: fp32 -> fp16 (one launch) -----------
__global__ __launch_bounds__(256) void conv_weights(
    const float* __restrict__ Km, const float* __restrict__ Wr,
    const float* __restrict__ Pz, const float* __restrict__ Pr)
{
    const size_t i = ((size_t)blockIdx.x * 256 + threadIdx.x) * 4;
    const float* src;
    __half* dst;
    size_t off;
    if (i < (size_t)Hdim * Hdim) { src = Km; dst = g_Kh; off = i; }
    else if (i < 2ull * Hdim * Hdim) {
        src = Wr; dst = g_Wh; off = i - (size_t)Hdim * Hdim;
    } else if (i < 2ull * Hdim * Hdim + (size_t)Hdim * INdim) {
        src = Pz; dst = g_Pzh; off = i - 2ull * Hdim * Hdim;
    } else {
        src = Pr; dst = g_Prh; off = i - 2ull * Hdim * Hdim - (size_t)Hdim * INdim;
    }
    float4 v = *(const float4*)&src[off];
    __half h[4] = { __float2half_rn(v.x), __float2half_rn(v.y),
                    __float2half_rn(v.z), __float2half_rn(v.w) };
    *(uint2*)&dst[off] = *(uint2*)h;
}

__global__ __launch_bounds__(256) void conv_x(const float* __restrict__ x) {
    const size_t i = ((size_t)blockIdx.x * 256 + threadIdx.x) * 4;
    float4 v = *(const float4*)&x[i];
    __half h[4] = { __float2half_rn(v.x), __float2half_rn(v.y),
                    __float2half_rn(v.z), __float2half_rn(v.w) };
    *(uint2*)&g_xh[i] = *(uint2*)h;
}

// ---------------- projection GEMM: Az/Ar[t] = P @ x_t --------------------
// Block tile 128x128, warp tile 32x64 (4x2 warps). grid (8, 2, 2*Tdim).
__global__ __launch_bounds__(256, 2) void proj_gemm() {
    extern __shared__ __half smh[];
    const int tid = threadIdx.x;
    const int warp = tid >> 5;
    const int wm = warp >> 1, wn = warp & 1;
    const int which = blockIdx.z & 1, q = blockIdx.z >> 1;
    const __half* A = which ? g_Prh : g_Pzh;
    const __half* B = g_xh + (size_t)q * XT_STRIDE;
    float* C = (which ? g_Ar : g_Az) + (size_t)q * HB;
    const int m0 = blockIdx.x * 128, n0 = blockIdx.y * 128;

    __half* const sA[2] = { smh, smh + SA_P };
    __half* const sB[2] = { smh + 2 * SA_P, smh + 2 * SA_P + SB_P };
    const uint32_t aB[2] = { s2u(sA[0]), s2u(sA[1]) };
    const uint32_t bB[2] = { s2u(sB[0]), s2u(sB[1]) };

    auto issue = [&](int c, int s) {
        const int kc = c * KCHUNK;
#pragma unroll
        for (int i = 0; i < 2; ++i) {
            const int e = i * 256 + tid, r = e >> 2, f8 = e & 3;
            cp_async16_ca(aB[s] + (uint32_t)(r * A_LDP + f8 * 8) * 2,
                          A + (size_t)(m0 + r) * INdim + kc + f8 * 8);
        }
#pragma unroll
        for (int i = 0; i < 2; ++i) {
            const int e = i * 256 + tid, r = e >> 4, f8 = e & 15;
            cp_async16_ca(bB[s] + (uint32_t)(r * B_LDP + f8 * 8) * 2,
                          B + (size_t)(kc + r) * Bdim + n0 + f8 * 8);
        }
        cp_commit();
    };

    wmma::fragment<wmma::accumulator, 16, 16, 16, float> acc[2][4];
#pragma unroll
    for (int i = 0; i < 2; ++i)
#pragma unroll
        for (int j = 0; j < 4; ++j) wmma::fill_fragment(acc[i][j], 0.0f);

    const int nChunks = INdim / KCHUNK;  // 16
    issue(0, 0);
    for (int c = 0; c < nChunks; ++c) {
        if (c + 1 < nChunks) { issue(c + 1, (c + 1) & 1); cp_wait<1>(); }
        else                 { cp_wait<0>(); }
        __syncthreads();
        const __half* cA = sA[c & 1];
        const __half* cB = sB[c & 1];
#pragma unroll
        for (int ks = 0; ks < 2; ++ks) {
            wmma::fragment<wmma::matrix_a, 16, 16, 16, __half,
                           wmma::row_major> af[2];
            wmma::fragment<wmma::matrix_b, 16, 16, 16, __half,
                           wmma::row_major> bf[4];
#pragma unroll
            for (int i = 0; i < 2; ++i)
                wmma::load_matrix_sync(af[i],
                    cA + (wm * 32 + i * 16) * A_LDP + ks * 16, A_LDP);
#pragma unroll
            for (int j = 0; j < 4; ++j)
                wmma::load_matrix_sync(bf[j],
                    cB + (ks * 16) * B_LDP + wn * 64 + j * 16, B_LDP);
#pragma unroll
            for (int i = 0; i < 2; ++i)
#pragma unroll
                for (int j = 0; j < 4; ++j)
                    wmma::mma_sync(acc[i][j], af[i], bf[j], acc[i][j]);
        }
        __syncthreads();
    }
    const int row = m0 + wm * 32, col = n0 + wn * 64;
#pragma unroll
    for (int i = 0; i < 2; ++i)
#pragma unroll
        for (int j = 0; j < 4; ++j)
            wmma::store_matrix_sync(
                C + (size_t)(row + i * 16) * Bdim + col + j * 16,
                acc[i][j], Bdim, wmma::mem_row_major);
}

// ---------------- persistent recurrence kernel ---------------------------
// 128 blocks x 256 threads, 1 block/SM (207KB smem). A-slice persistent in
// smem; FULL per-step B slice prefetched in 2 cp.async groups. R11 structure
// with SPLIT arrive/wait barriers: private work (Az/Ar prefetch, v staging,
// X/U update) overlaps barrier arrival of other blocks.
__global__ __launch_bounds__(256, 1) void recurrence(
    const float* __restrict__ c_x, const float* __restrict__ c_u,
    const float* __restrict__ c_U, const float* __restrict__ gz,
    const float* __restrict__ br)
{
    extern __shared__ __half smh[];
    const int tid = threadIdx.x;
    const int bid = blockIdx.x;

    // ----- elem identity: 8 consecutive elements of [H][B] -----
    const int idx = (bid * 256 + tid) * 8;
    const int h = idx >> 8;
    const float zx = 0.001f + 0.099f * sigm(c_x[h]);
    const float zu = 0.001f + 0.099f * sigm(c_u[h]);
    const float Uc = 0.9f * sigm(c_U[h]);
    const float gzh = gz[h], brh = br[h];
    float v[8], X[8], U[8];
#pragma unroll
    for (int e = 0; e < 8; ++e) { v[e] = 0.f; X[e] = 1.f; U[e] = 0.9f; }

    // ----- gemm identity: 128 blocks = mb8 x nb4 x which2 x q2 -----
    const int which = bid & 1;
    const int q = (bid >> 1) & 1;
    const int nb = (bid >> 2) & 3;
    const int mb = bid >> 4;
    const int warp = tid >> 5;
    const int wm = warp >> 1, wn = warp & 1;
    const __half* Ag = which ? g_Wh : g_Kh;
    const __half* Bg = which ? g_mh : g_rh;
    float* Cg = (which ? g_G2p : g_G1p) + (size_t)q * HB;
    const int kStart = q * (Hdim / KSPLIT);   // 0 or 512
    const int m0 = mb * 128, n0 = nb * 64;

    __half* const sA = smh;               // persistent 128 x A_LDR
    __half* const sB = smh + SA_R;        // full 512 x B_LDR
    const uint32_t aBase = s2u(sA);
    const uint32_t bBase = s2u(sB);

    // ----- one-time A-slice load -----
    {
        const __half* Asrc = Ag + (size_t)m0 * Hdim + kStart;
#pragma unroll
        for (int i = 0; i < 32; ++i) {
            const int e = i * 256 + tid, r = e >> 6, g = e & 63;
            cp_async16_ca(aBase + (uint32_t)(r * A_LDR + g * 8) * 2,
                          Asrc + (size_t)r * Hdim + g * 8);
        }
        cp_commit();
        cp_wait<0>();
        __syncthreads();
    }

    // per-chunk B load: 32 rows x 8 granules = 256 cp.async (1/thread)
    const int brow = tid >> 3, bg8 = tid & 7;
    auto issueB = [&](int c) {
        const int kc = kStart + c * KCHUNK;
        cp_async16_cg(
            bBase + (uint32_t)((c * KCHUNK + brow) * B_LDR + bg8 * 8) * 2,
            Bg + (size_t)(kc + brow) * Bdim + n0 + bg8 * 8);
    };

    // ----- initial elem (t = 0): v=0 -> r, m -----
    {
        __half rr[8], mm[8];
#pragma unroll
        for (int e = 0; e < 8; ++e) {
            const float r = sigm(v[e]);
            float Xn = zx + (1.0f - zx) * X[e] - U[e] * X[e] * r;
            float Un = Uc * zu + (1.0f - zu) * U[e] + Uc * (1.0f - U[e]) * r;
            Un = fminf(fmaxf(Un, Uc), 1.0f);
            X[e] = Xn;
            U[e] = Un;
            rr[e] = __float2half_rn(r);
            mm[e] = __float2half_rn(Un * Xn * r);
        }
        *(uint4*)&g_rh[idx] = *(uint4*)rr;
        *(uint4*)&g_mh[idx] = *(uint4*)mm;
    }
    grid_sync();

    for (int t = 0; t < Tdim; ++t) {
        // ===== gemm phase: C_q = A_slice @ B[kStart:+512, n0:+64] =====
        float az[8], ar[8];
        {
            // prefetch FULL B: chunks 0-3 -> group 0, 4-15 -> group 1
#pragma unroll
            for (int c = 0; c < 4; ++c) issueB(c);
            cp_commit();
#pragma unroll
            for (int c = 4; c < 16; ++c) issueB(c);
            cp_commit();

            wmma::fragment<wmma::accumulator, 16, 16, 16, float> acc[2][2];
#pragma unroll
            for (int i = 0; i < 2; ++i)
#pragma unroll
                for (int j = 0; j < 2; ++j) wmma::fill_fragment(acc[i][j], 0.0f);

            cp_wait<1>();
            __syncthreads();
#pragma unroll 2
            for (int c = 0; c < 4; ++c) {
#pragma unroll
                for (int ks = 0; ks < 2; ++ks) {
                    wmma::fragment<wmma::matrix_a, 16, 16, 16, __half,
                                   wmma::row_major> af[2];
                    wmma::fragment<wmma::matrix_b, 16, 16, 16, __half,
                                   wmma::row_major> bf[2];
#pragma unroll
                    for (int i = 0; i < 2; ++i)
                        wmma::load_matrix_sync(af[i],
                            sA + (wm * 32 + i * 16) * A_LDR + c * 32 + ks * 16,
                            A_LDR);
#pragma unroll
                    for (int j = 0; j < 2; ++j)
                        wmma::load_matrix_sync(bf[j],
                            sB + (c * 32 + ks * 16) * B_LDR + wn * 32 + j * 16,
                            B_LDR);
#pragma unroll
                    for (int i = 0; i < 2; ++i)
#pragma unroll
                        for (int j = 0; j < 2; ++j)
                            wmma::mma_sync(acc[i][j], af[i], bf[j], acc[i][j]);
                }
            }
            cp_wait<0>();
            __syncthreads();
#pragma unroll 2
            for (int c = 4; c < 16; ++c) {
#pragma unroll
                for (int ks = 0; ks < 2; ++ks) {
                    wmma::fragment<wmma::matrix_a, 16, 16, 16, __half,
                                   wmma::row_major> af[2];
                    wmma::fragment<wmma::matrix_b, 16, 16, 16, __half,
                                   wmma::row_major> bf[2];
#pragma unroll
                    for (int i = 0; i < 2; ++i)
                        wmma::load_matrix_sync(af[i],
                            sA + (wm * 32 + i * 16) * A_LDR + c * 32 + ks * 16,
                            A_LDR);
#pragma unroll
                    for (int j = 0; j < 2; ++j)
                        wmma::load_matrix_sync(bf[j],
                            sB + (c * 32 + ks * 16) * B_LDR + wn * 32 + j * 16,
                            B_LDR);
#pragma unroll
                    for (int i = 0; i < 2; ++i)
#pragma unroll
                        for (int j = 0; j < 2; ++j)
                            wmma::mma_sync(acc[i][j], af[i], bf[j], acc[i][j]);
                }
            }
            const int row = m0 + wm * 32, col = n0 + wn * 32;
#pragma unroll
            for (int i = 0; i < 2; ++i)
#pragma unroll
                for (int j = 0; j < 2; ++j)
                    wmma::store_matrix_sync(
                        Cg + (size_t)(row + i * 16) * Bdim + col + j * 16,
                        acc[i][j], Bdim, wmma::mem_row_major);
        }
        // arrive (publishes partial stores), THEN prefetch Az/Ar (private),
        // then wait — the prefetch overlaps other blocks' arrivals.
        {
            unsigned long long bt = grid_arrive();
            const size_t off = (size_t)t * HB + idx;
            *(float4*)&az[0] = *(const float4*)&g_Az[off];
            *(float4*)&az[4] = *(const float4*)&g_Az[off + 4];
            *(float4*)&ar[0] = *(const float4*)&g_Ar[off];
            *(float4*)&ar[4] = *(const float4*)&g_Ar[off + 4];
            grid_wait(bt);
        }

        // ===== elem phase =====
        {
            const size_t off = (size_t)t * HB + idx;
            float s1[8], s2[8], tmp[4];
#pragma unroll
            for (int g = 0; g < 2; ++g) {
                *(float4*)&s1[g * 4] = __ldcg((const float4*)&g_G1p[idx + g * 4]);
                *(float4*)&s2[g * 4] = __ldcg((const float4*)&g_G2p[idx + g * 4]);
                *(float4*)tmp = __ldcg((const float4*)&g_G1p[HB + idx + g * 4]);
#pragma unroll
                for (int e = 0; e < 4; ++e) s1[g * 4 + e] += tmp[e];
                *(float4*)tmp = __ldcg((const float4*)&g_G2p[HB + idx + g * 4]);
#pragma unroll
                for (int e = 0; e < 4; ++e) s2[g * 4 + e] += tmp[e];
            }
#pragma unroll
            for (int e = 0; e < 8; ++e) {
                float zt = 0.1f * sigm(s1[e] + az[e] + gzh);
                v[e] = (1.0f - zt) * v[e] + 0.1f * (s2[e] + ar[e] + brh);
            }

            if (t + 1 < Tdim) {
                // publish r/m FIRST (the only data other blocks need) ...
                __half rr[8], mm[8];
                float Xn[8], Un[8];
#pragma unroll
                for (int e = 0; e < 8; ++e) {
                    const float r = sigm(v[e]);
                    Xn[e] = zx + (1.0f - zx) * X[e] - U[e] * X[e] * r;
                    Un[e] = Uc * zu + (1.0f - zu) * U[e] +
                            Uc * (1.0f - U[e]) * r;
                    Un[e] = fminf(fmaxf(Un[e], Uc), 1.0f);
                    rr[e] = __float2half_rn(r);
                    mm[e] = __float2half_rn(Un[e] * Xn[e] * r);
                }
                *(uint4*)&g_rh[idx] = *(uint4*)rr;
                *(uint4*)&g_mh[idx] = *(uint4*)mm;
                // ... arrive, then do private bookkeeping under the barrier
                unsigned long long bt = grid_arrive();
                __stcs((float4*)&g_Az[off], *(float4*)&v[0]);
                __stcs((float4*)&g_Az[off + 4], *(float4*)&v[4]);
#pragma unroll
                for (int e = 0; e < 8; ++e) { X[e] = Xn[e]; U[e] = Un[e]; }
                grid_wait(bt);
            } else {
                __stcs((float4*)&g_Az[off], *(float4*)&v[0]);
                __stcs((float4*)&g_Az[off + 4], *(float4*)&v[4]);
            }
        }
    }
}

// ---------------- final transpose: g_Az[t][h][b] -> out[t][b][h] ---------
__global__ __launch_bounds__(256) void transpose_out(float* __restrict__ out) {
    __shared__ float tile[32][33];
    const int t = blockIdx.z;
    const int h0 = blockIdx.y * 32;
    const int b0 = blockIdx.x * 32;
    const float* src = g_Az + (size_t)t * HB;
    float* dst = out + (size_t)t * HB;
    const int lx = threadIdx.x, ly = threadIdx.y;
#pragma unroll
    for (int i = 0; i < 32; i += 8)
        tile[ly + i][lx] = src[(size_t)(h0 + ly + i) * Bdim + b0 + lx];
    __syncthreads();
#pragma unroll
    for (int i = 0; i < 32; i += 8)
        dst[(size_t)(b0 + ly + i) * Hdim + h0 + lx] = tile[lx][ly + i];
}

// ---------------- launch ----------------
extern "C" void kernel_launch(void* const* d_in, const int* in_sizes, int n_in,
                              void* d_out, int out_size)
{
    const float* x   = (const float*)d_in[0];  // (T, IN, B)
    const float* c_x = (const float*)d_in[1];
    const float* c_u = (const float*)d_in[2];
    const float* c_U = (const float*)d_in[3];
    const float* w_r = (const float*)d_in[4];  // (H,H)
    const float* p_r = (const float*)d_in[5];  // (H,IN)
    const float* b_r = (const float*)d_in[6];
    const float* g_z = (const float*)d_in[7];
    const float* Km  = (const float*)d_in[8];  // (H,H)
    const float* p_z = (const float*)d_in[9];  // (H,IN)
    float* out = (float*)d_out;                // (T, B, H)

    cudaFuncSetAttribute(proj_gemm,
                         cudaFuncAttributeMaxDynamicSharedMemorySize, SMEM_PROJ);
    cudaFuncSetAttribute(recurrence,
                         cudaFuncAttributeMaxDynamicSharedMemorySize, SMEM_REC);

    conv_weights<<<(2 * Hdim * Hdim + 2 * Hdim * INdim) / 1024, 256>>>(
        Km, w_r, p_z, p_r);
    conv_x<<<(int)(((size_t)Tdim * XT_STRIDE) / 1024), 256>>>(x);
    proj_gemm<<<dim3(8, 2, 2 * Tdim), 256, SMEM_PROJ>>>();
    recurrence<<<NBLOCKS, 256, SMEM_REC>>>(c_x, c_u, c_U, g_z, b_r);
    transpose_out<<<dim3(Bdim / 32, Hdim / 32, Tdim), dim3(32, 8)>>>(out);
}